// round 7
// baseline (speedup 1.0000x reference)
#include <cuda_runtime.h>
#include <math.h>
#include <stdint.h>

// Problem shapes (fixed by setup_inputs)
#define NCELL 128
#define DN    64
#define AA    4
#define HM    128
#define TT    16
#define BB    8
#define SR    68    // row stride, 64-wide fp32 tiles (272B = 17*16B, float4/ull2 aligned)
#define W1S   68    // w1 [128 hm][64 k] padded
#define W2S   132   // w2 [64 d][128 hm] padded (528B = 33*16B)
#define NTHR  512

// ---- shared memory layout (floats); per-cell buffers 2 x 4352 ----
#define F_H    0        // h, neuron-major [n][d]
#define F_HEB  8704     // hebbian [i][j]
#define F_MF   17408    // union: hF (feature-major h [d][n]) during scatter->B, then m [i][d]
#define F_H2   26112    // union: W0 staging [i][j], then hid half [i][u]
#define F_W1   34816    // 128*68 = 8704
#define F_W2   43520    // 64*132 = 8448
#define F_XT   51968    // 2 x 64
#define F_INJ  52096    // 2 x 256
#define F_G    52608
#define F_HG   52736
#define F_WG1  52864
#define F_DF   52992
#define F_B1   53120
#define F_B2   53248
#define F_IP   53312
#define SMEMF  53328    // 213,312 bytes

#define HBAR() asm volatile("bar.sync %0, %1;" :: "r"(hf + 1), "n"(256) : "memory")

typedef unsigned long long u64t;
typedef ulonglong2 ull2;

__device__ __forceinline__ float sigf(float x) { return 1.0f / (1.0f + expf(-x)); }

__device__ __forceinline__ u64t fma2(u64t a, u64t b, u64t c) {
    u64t d;
    asm("fma.rn.f32x2 %0, %1, %2, %3;" : "=l"(d) : "l"(a), "l"(b), "l"(c));
    return d;
}
__device__ __forceinline__ u64t pk2(float lo, float hi) {
    u64t r;
    asm("mov.b64 %0, {%1, %2};" : "=l"(r) : "f"(lo), "f"(hi));
    return r;
}
__device__ __forceinline__ float lhsum(u64t v) {
    float lo, hi;
    asm("mov.b64 {%0, %1}, %2;" : "=f"(lo), "=f"(hi) : "l"(v));
    return lo + hi;
}

// C1 half: hid[i][u] = tanh( sum_k m[i][k]*w1[h0+u][k] + b1[h0+u] )
__device__ __forceinline__ void mlp_c1(const float* __restrict__ sM,
                                       const float* __restrict__ sW1,
                                       const float* __restrict__ sB1,
                                       float* __restrict__ sHid,
                                       int r0, int cb, int h0)
{
    u64t acc[2][8];
    #pragma unroll
    for (int ii = 0; ii < 2; ++ii)
        #pragma unroll
        for (int uu = 0; uu < 8; ++uu) acc[ii][uu] = 0ull;

    #pragma unroll 4
    for (int k4 = 0; k4 < 16; ++k4) {
        ull2 wv[8];
        #pragma unroll
        for (int uu = 0; uu < 8; ++uu)
            wv[uu] = *(const ull2*)&sW1[(h0 + cb + uu) * W1S + k4 * 4];
        #pragma unroll
        for (int ii = 0; ii < 2; ++ii) {
            ull2 mv = *(const ull2*)&sM[(r0 + ii) * SR + k4 * 4];
            #pragma unroll
            for (int uu = 0; uu < 8; ++uu) {
                acc[ii][uu] = fma2(mv.x, wv[uu].x, acc[ii][uu]);
                acc[ii][uu] = fma2(mv.y, wv[uu].y, acc[ii][uu]);
            }
        }
    }
    #pragma unroll
    for (int ii = 0; ii < 2; ++ii) {
        float v[8];
        #pragma unroll
        for (int uu = 0; uu < 8; ++uu)
            v[uu] = tanhf(lhsum(acc[ii][uu]) + sB1[h0 + cb + uu]);
        *(float4*)&sHid[(r0 + ii) * SR + cb]     = make_float4(v[0], v[1], v[2], v[3]);
        *(float4*)&sHid[(r0 + ii) * SR + cb + 4] = make_float4(v[4], v[5], v[6], v[7]);
    }
}

// C2 half: accC[ii][d] += sum_u hid[i][u]*w2[d][h0+u]
__device__ __forceinline__ void mlp_c2(const float* __restrict__ sHid,
                                       const float* __restrict__ sW2,
                                       float accC[2][8],
                                       int r0, int cb, int h0)
{
    u64t acc[2][8];
    #pragma unroll
    for (int ii = 0; ii < 2; ++ii)
        #pragma unroll
        for (int dd = 0; dd < 8; ++dd) acc[ii][dd] = 0ull;

    #pragma unroll 4
    for (int u4 = 0; u4 < 16; ++u4) {
        ull2 wv[8];
        #pragma unroll
        for (int dd = 0; dd < 8; ++dd)
            wv[dd] = *(const ull2*)&sW2[(cb + dd) * W2S + h0 + u4 * 4];
        #pragma unroll
        for (int ii = 0; ii < 2; ++ii) {
            ull2 hv = *(const ull2*)&sHid[(r0 + ii) * SR + u4 * 4];
            #pragma unroll
            for (int dd = 0; dd < 8; ++dd) {
                acc[ii][dd] = fma2(hv.x, wv[dd].x, acc[ii][dd]);
                acc[ii][dd] = fma2(hv.y, wv[dd].y, acc[ii][dd]);
            }
        }
    }
    #pragma unroll
    for (int ii = 0; ii < 2; ++ii)
        #pragma unroll
        for (int dd = 0; dd < 8; ++dd)
            accC[ii][dd] += lhsum(acc[ii][dd]);
}

__global__ void __launch_bounds__(NTHR, 1)
memgraph_kernel(const float* __restrict__ x,
                const float* __restrict__ h0,
                const float* __restrict__ W0,
                const float* __restrict__ heb0,
                const float* __restrict__ neuron_id,
                const float* __restrict__ msg_w1,
                const float* __restrict__ msg_b1,
                const float* __restrict__ msg_w2,
                const float* __restrict__ msg_b2,
                const float* __restrict__ inject_w,
                const float* __restrict__ inject_b,
                const float* __restrict__ Wdl,
                const float* __restrict__ dgl,
                const float* __restrict__ hdl,
                const int*   __restrict__ ipi,
                const int*   __restrict__ opi,
                float* __restrict__ out)
{
    extern __shared__ float sm[];

    const int tid  = threadIdx.x;
    const int hf   = tid >> 8;
    const int htid = tid & 255;

    const int blk = blockIdx.x;
    const int b   = blk >> 6;
    const int c   = (blk & 63) * 2 + hf;
    const int bc  = b * NCELL + c;

    float* sH   = sm + F_H   + hf * 4352;
    float* sHeb = sm + F_HEB + hf * 4352;
    float* sMF  = sm + F_MF  + hf * 4352;   // hF then m
    float* sH2  = sm + F_H2  + hf * 4352;   // W0 stage then hid
    float* sW1  = sm + F_W1;
    float* sW2  = sm + F_W2;
    float* sXt  = sm + F_XT  + hf * 64;
    float* sInj = sm + F_INJ + hf * 256;
    float* sG   = sm + F_G   + hf * 64;
    float* sHg  = sm + F_HG  + hf * 64;
    float* sWg1 = sm + F_WG1 + hf * 64;
    float* sDf  = sm + F_DF  + hf * 64;
    float* sB1  = sm + F_B1;
    float* sB2  = sm + F_B2;
    int*   sIP  = (int*)(sm + F_IP) + hf * 8;

    // ---- init: shared weights, ORIGINAL (reduction-contiguous) layouts ----
    for (int idx = tid; idx < HM * DN; idx += NTHR) {
        int hm = idx >> 6, k = idx & 63;
        sW1[hm * W1S + k] = msg_w1[idx];           // w1[hm][k], k-contig
    }
    for (int idx = tid; idx < DN * HM; idx += NTHR) {
        int d = idx >> 7, hm = idx & 127;
        sW2[d * W2S + hm] = msg_w2[idx];           // w2[d][hm], hm-contig
    }
    if (tid < HM) sB1[tid] = msg_b1[tid];
    if (tid < 64) sB2[tid] = msg_b2[tid];

    // ---- init: per-cell state (+ feature-major hF copy) ----
    const size_t base4 = (size_t)bc * 4096;
    for (int idx = htid; idx < 4096; idx += 256) {
        int i = idx >> 6, d = idx & 63;
        float hv = h0[base4 + idx];
        sH  [i * SR + d] = hv;
        sMF [d * SR + i] = hv;                     // hF[d][n]
        sHeb[i * SR + d] = heb0[base4 + idx];
    }
    if (htid < 64) {
        sG  [htid] = 0.5f * sigf(dgl[c * 64 + htid]);
        sHg [htid] = 0.5f * sigf(hdl[c * 64 + htid]);
        sWg1[htid] = 1.0f - 0.5f * sigf(Wdl[c * 64 + htid]);
        sDf [htid] = 1.0f;
        sXt [htid] = x[(((size_t)b * TT + 0) * NCELL + c) * 64 + htid];
    }
    if (htid < AA) {
        sIP[htid]     = ipi[c * AA + htid];
        sIP[4 + htid] = opi[c * AA + htid];
    }
    __syncthreads();

    const int tr = htid >> 3;        // 0..31 -> rows r0=2*tr
    const int tc = htid & 7;         // 0..7  -> cols cb=8*tc
    const int r0 = tr * 2;
    const int cb = tc * 8;
    const float* Wbase = W0 + base4;

    for (int t = 0; t < TT; ++t) {
        // ---- P0: stage W0 -> sH2 (coalesced) and compute injection ----
        #pragma unroll
        for (int q = 0; q < 4; ++q) {
            int lin = q * 256 + htid;
            int i = lin >> 4, col = (lin & 15) * 4;
            float4 w = __ldg((const float4*)(Wbase + i * 64 + col));
            *(float4*)&sH2[i * SR + col] = w;
        }
        {
            int aa = htid >> 6, d = htid & 63;
            int row = aa * 64 + d;
            const float4* wr  = (const float4*)(inject_w + ((size_t)c * 256 + row) * 64);
            const float4* xt4 = (const float4*)sXt;
            float s = inject_b[c * 256 + row];
            #pragma unroll 4
            for (int k = 0; k < 16; ++k) {
                float4 w = __ldg(wr + k);
                float4 xv = xt4[k];
                s += w.x * xv.x + w.y * xv.y + w.z * xv.z + w.w * xv.w;
            }
            sInj[htid] = s;
        }
        HBAR();

        // ---- scatter inj onto input ports of h AND hF (deterministic) ----
        if (htid < 64) {
            #pragma unroll
            for (int aa = 0; aa < AA; ++aa) {
                int p = sIP[aa];
                float v = sInj[aa * 64 + htid];
                sH [p * SR + htid] += v;
                sMF[htid * SR + p] += v;           // hF[d][p]
            }
        }
        HBAR();

        // ---- B: m[i][d] = sum_j (df*W0 + heb)[i][j] * hF[d][j]  (f32x2 dot) ----
        u64t accB[2][8];
        {
            u64t df2[2];
            df2[0] = pk2(sDf[r0], sDf[r0]);
            df2[1] = pk2(sDf[r0 + 1], sDf[r0 + 1]);
            #pragma unroll
            for (int ii = 0; ii < 2; ++ii)
                #pragma unroll
                for (int dd = 0; dd < 8; ++dd) accB[ii][dd] = 0ull;

            #pragma unroll 4
            for (int j4 = 0; j4 < 16; ++j4) {
                ull2 hfv[8];
                #pragma unroll
                for (int dd = 0; dd < 8; ++dd)
                    hfv[dd] = *(const ull2*)&sMF[(cb + dd) * SR + j4 * 4];
                #pragma unroll
                for (int ii = 0; ii < 2; ++ii) {
                    ull2 wv = *(const ull2*)&sH2 [(r0 + ii) * SR + j4 * 4];
                    ull2 hb = *(const ull2*)&sHeb[(r0 + ii) * SR + j4 * 4];
                    u64t f0 = fma2(wv.x, df2[ii], hb.x);
                    u64t f1 = fma2(wv.y, df2[ii], hb.y);
                    #pragma unroll
                    for (int dd = 0; dd < 8; ++dd) {
                        accB[ii][dd] = fma2(f0, hfv[dd].x, accB[ii][dd]);
                        accB[ii][dd] = fma2(f1, hfv[dd].y, accB[ii][dd]);
                    }
                }
            }
        }
        HBAR();   // all hF reads done; sMF can be overwritten with m

        #pragma unroll
        for (int ii = 0; ii < 2; ++ii) {
            *(float4*)&sMF[(r0 + ii) * SR + cb] =
                make_float4(lhsum(accB[ii][0]), lhsum(accB[ii][1]),
                            lhsum(accB[ii][2]), lhsum(accB[ii][3]));
            *(float4*)&sMF[(r0 + ii) * SR + cb + 4] =
                make_float4(lhsum(accB[ii][4]), lhsum(accB[ii][5]),
                            lhsum(accB[ii][6]), lhsum(accB[ii][7]));
        }
        HBAR();

        // ---- shared MLP, two hm-halves; hid lives in sH2 (W0 stage dead) ----
        float accC[2][8];
        #pragma unroll
        for (int ii = 0; ii < 2; ++ii)
            #pragma unroll
            for (int dd = 0; dd < 8; ++dd) accC[ii][dd] = 0.0f;

        mlp_c1(sMF, sW1, sB1, sH2, r0, cb, 0);
        HBAR();
        mlp_c2(sH2, sW2, accC, r0, cb, 0);
        HBAR();
        mlp_c1(sMF, sW1, sB1, sH2, r0, cb, 64);
        HBAR();
        mlp_c2(sH2, sW2, accC, r0, cb, 64);

        // ---- gated h update; rewrite sH rows and hF (into sMF, m now dead) ----
        {
            float4 bv0 = *(const float4*)&sB2[cb];
            float4 bv1 = *(const float4*)&sB2[cb + 4];
            #pragma unroll
            for (int ii = 0; ii < 2; ++ii) {
                int r = r0 + ii;
                const float* nidp = neuron_id + (size_t)c * 4096 + r * 64 + cb;
                float4 nv0 = __ldg((const float4*)nidp);
                float4 nv1 = __ldg((const float4*)(nidp + 4));
                float g = sG[r];
                float* hr = &sH[r * SR + cb];
                float hn[8];
                hn[0] = (1.0f - g) * hr[0] + g * tanhf(accC[ii][0] + bv0.x + nv0.x);
                hn[1] = (1.0f - g) * hr[1] + g * tanhf(accC[ii][1] + bv0.y + nv0.y);
                hn[2] = (1.0f - g) * hr[2] + g * tanhf(accC[ii][2] + bv0.z + nv0.z);
                hn[3] = (1.0f - g) * hr[3] + g * tanhf(accC[ii][3] + bv0.w + nv0.w);
                hn[4] = (1.0f - g) * hr[4] + g * tanhf(accC[ii][4] + bv1.x + nv1.x);
                hn[5] = (1.0f - g) * hr[5] + g * tanhf(accC[ii][5] + bv1.y + nv1.y);
                hn[6] = (1.0f - g) * hr[6] + g * tanhf(accC[ii][6] + bv1.z + nv1.z);
                hn[7] = (1.0f - g) * hr[7] + g * tanhf(accC[ii][7] + bv1.w + nv1.w);
                *(float4*)&hr[0] = make_float4(hn[0], hn[1], hn[2], hn[3]);
                *(float4*)&hr[4] = make_float4(hn[4], hn[5], hn[6], hn[7]);
                // hF transpose write, tc-rotated to spread banks
                #pragma unroll
                for (int j0 = 0; j0 < 8; ++j0) {
                    int jj = (j0 + tc) & 7;
                    sMF[(cb + jj) * SR + r] = hn[jj];
                }
            }
        }
        HBAR();

        // ---- D: heb[i][j] update via f32x2 dot over d (both operands natural) ----
        {
            u64t acc[2][8];
            #pragma unroll
            for (int ii = 0; ii < 2; ++ii)
                #pragma unroll
                for (int jj = 0; jj < 8; ++jj) acc[ii][jj] = 0ull;

            #pragma unroll 4
            for (int d4 = 0; d4 < 16; ++d4) {
                ull2 vv[8];
                #pragma unroll
                for (int jj = 0; jj < 8; ++jj)
                    vv[jj] = *(const ull2*)&sH[(cb + jj) * SR + d4 * 4];
                #pragma unroll
                for (int ii = 0; ii < 2; ++ii) {
                    ull2 uv = *(const ull2*)&sH[(r0 + ii) * SR + d4 * 4];
                    #pragma unroll
                    for (int jj = 0; jj < 8; ++jj) {
                        acc[ii][jj] = fma2(uv.x, vv[jj].x, acc[ii][jj]);
                        acc[ii][jj] = fma2(uv.y, vv[jj].y, acc[ii][jj]);
                    }
                }
            }
            #pragma unroll
            for (int ii = 0; ii < 2; ++ii) {
                int i = r0 + ii;
                float hg1 = 1.0f - sHg[i];
                float hgs = sHg[i] * (1.0f / 64.0f);   // (Dn^-0.5)^2 folded
                float* hebr = &sHeb[i * SR + cb];
                float4 o0 = *(const float4*)&hebr[0];
                float4 o1 = *(const float4*)&hebr[4];
                float nh[8];
                nh[0] = hg1 * o0.x + hgs * lhsum(acc[ii][0]);
                nh[1] = hg1 * o0.y + hgs * lhsum(acc[ii][1]);
                nh[2] = hg1 * o0.z + hgs * lhsum(acc[ii][2]);
                nh[3] = hg1 * o0.w + hgs * lhsum(acc[ii][3]);
                nh[4] = hg1 * o1.x + hgs * lhsum(acc[ii][4]);
                nh[5] = hg1 * o1.y + hgs * lhsum(acc[ii][5]);
                nh[6] = hg1 * o1.z + hgs * lhsum(acc[ii][6]);
                nh[7] = hg1 * o1.w + hgs * lhsum(acc[ii][7]);
                if (i >= cb && i < cb + 8) nh[i - cb] = 0.0f;   // off-diagonal mask
                *(float4*)&hebr[0] = make_float4(nh[0], nh[1], nh[2], nh[3]);
                *(float4*)&hebr[4] = make_float4(nh[4], nh[5], nh[6], nh[7]);
            }
        }

        // ---- readout / decay / next-xt prefetch (disjoint thread sets) ----
        if (htid < 64) {
            float s = 0.0f;
            #pragma unroll
            for (int aa = 0; aa < AA; ++aa)
                s += sH[sIP[4 + aa] * SR + htid];
            out[(((size_t)b * TT + t) * NCELL + c) * 64 + htid] = 0.125f * s;
        } else if (htid < 128) {
            sDf[htid - 64] *= sWg1[htid - 64];
        } else if (htid >= 192 && t + 1 < TT) {
            sXt[htid - 192] = x[(((size_t)b * TT + t + 1) * NCELL + c) * 64 + (htid - 192)];
        }
        HBAR();
    }
}

extern "C" void kernel_launch(void* const* d_in, const int* in_sizes, int n_in,
                              void* d_out, int out_size)
{
    (void)in_sizes; (void)n_in; (void)out_size;
    const float* x         = (const float*)d_in[0];
    const float* h0        = (const float*)d_in[1];
    const float* W0        = (const float*)d_in[2];
    const float* heb0      = (const float*)d_in[3];
    const float* neuron_id = (const float*)d_in[4];
    const float* msg_w1    = (const float*)d_in[5];
    const float* msg_b1    = (const float*)d_in[6];
    const float* msg_w2    = (const float*)d_in[7];
    const float* msg_b2    = (const float*)d_in[8];
    const float* inject_w  = (const float*)d_in[9];
    const float* inject_b  = (const float*)d_in[10];
    const float* Wdl       = (const float*)d_in[11];
    const float* dgl       = (const float*)d_in[12];
    const float* hdl       = (const float*)d_in[13];
    const int*   ipi       = (const int*)d_in[14];
    const int*   opi       = (const int*)d_in[15];
    float* out = (float*)d_out;

    size_t smem_bytes = (size_t)SMEMF * sizeof(float);   // 213,312 B
    cudaFuncSetAttribute(memgraph_kernel,
                         cudaFuncAttributeMaxDynamicSharedMemorySize,
                         (int)smem_bytes);

    memgraph_kernel<<<(BB * NCELL) / 2, NTHR, smem_bytes>>>(
        x, h0, W0, heb0, neuron_id, msg_w1, msg_b1, msg_w2, msg_b2,
        inject_w, inject_b, Wdl, dgl, hdl, ipi, opi, out);
}

// round 9
// speedup vs baseline: 6.7178x; 6.7178x over previous
#include <cuda_runtime.h>
#include <math.h>
#include <stdint.h>

// Problem shapes (fixed by setup_inputs)
#define NCELL 128
#define DN    64
#define AA    4
#define HM    128
#define TT    16
#define BB    8
#define SR    68    // row stride, 64-wide fp32 tiles (272B, 16B-aligned rows)
#define W1S   68    // w1 [128 hm][64 k] padded (k-contiguous)
#define W2S   132   // w2 [64 d][128 hm] padded (hm-contiguous)
#define NTHR  512

// ---- shared memory layout (floats); per-cell buffers 2 x 4352 ----
#define F_H    0        // h [n][d]
#define F_HEB  8704     // hebbian [i][j]
#define F_MF   17408    // union: hF (h transposed [d][n]) scatter->B, then m [i][d]
#define F_H2   26112    // union: W0 staging [i][j], then hid half [i][u]
#define F_W1   34816    // 128*68 = 8704
#define F_W2   43520    // 64*132 = 8448
#define F_XT   51968
#define F_INJ  52096
#define F_G    52608
#define F_HG   52736
#define F_WG1  52864
#define F_DF   52992
#define F_B1   53120
#define F_B2   53248
#define F_IP   53312
#define SMEMF  53328    // 213,312 bytes

#define HBAR() asm volatile("bar.sync %0, %1;" :: "r"(hf + 1), "n"(256) : "memory")

typedef unsigned long long u64t;
typedef ulonglong2 ull2;

__device__ __forceinline__ float sigf(float x) { return 1.0f / (1.0f + expf(-x)); }

__device__ __forceinline__ u64t fma2(u64t a, u64t b, u64t c) {
    u64t d;
    asm("fma.rn.f32x2 %0, %1, %2, %3;" : "=l"(d) : "l"(a), "l"(b), "l"(c));
    return d;
}
__device__ __forceinline__ u64t pk2(float lo, float hi) {
    u64t r;
    asm("mov.b64 %0, {%1, %2};" : "=l"(r) : "f"(lo), "f"(hi));
    return r;
}
__device__ __forceinline__ float lhsum(u64t v) {
    float lo, hi;
    asm("mov.b64 {%0, %1}, %2;" : "=f"(lo), "=f"(hi) : "l"(v));
    return lo + hi;
}

__global__ void __launch_bounds__(NTHR, 1)
memgraph_kernel(const float* __restrict__ x,
                const float* __restrict__ h0,
                const float* __restrict__ W0,
                const float* __restrict__ heb0,
                const float* __restrict__ neuron_id,
                const float* __restrict__ msg_w1,
                const float* __restrict__ msg_b1,
                const float* __restrict__ msg_w2,
                const float* __restrict__ msg_b2,
                const float* __restrict__ inject_w,
                const float* __restrict__ inject_b,
                const float* __restrict__ Wdl,
                const float* __restrict__ dgl,
                const float* __restrict__ hdl,
                const int*   __restrict__ ipi,
                const int*   __restrict__ opi,
                float* __restrict__ out)
{
    extern __shared__ float sm[];

    const int tid  = threadIdx.x;
    const int hf   = tid >> 8;
    const int htid = tid & 255;

    const int blk = blockIdx.x;
    const int b   = blk >> 6;
    const int c   = (blk & 63) * 2 + hf;
    const int bc  = b * NCELL + c;

    float* sH   = sm + F_H   + hf * 4352;
    float* sHeb = sm + F_HEB + hf * 4352;
    float* sMF  = sm + F_MF  + hf * 4352;
    float* sH2  = sm + F_H2  + hf * 4352;
    float* sW1  = sm + F_W1;
    float* sW2  = sm + F_W2;
    float* sXt  = sm + F_XT  + hf * 64;
    float* sInj = sm + F_INJ + hf * 256;
    float* sG   = sm + F_G   + hf * 64;
    float* sHg  = sm + F_HG  + hf * 64;
    float* sWg1 = sm + F_WG1 + hf * 64;
    float* sDf  = sm + F_DF  + hf * 64;
    float* sB1  = sm + F_B1;
    float* sB2  = sm + F_B2;
    int*   sIP  = (int*)(sm + F_IP) + hf * 8;

    // ---- init: shared weights in reduction-contiguous layouts ----
    for (int idx = tid; idx < HM * DN; idx += NTHR) {
        int hm = idx >> 6, k = idx & 63;
        sW1[hm * W1S + k] = msg_w1[idx];           // w1[hm][k]
    }
    for (int idx = tid; idx < DN * HM; idx += NTHR) {
        int d = idx >> 7, hm = idx & 127;
        sW2[d * W2S + hm] = msg_w2[idx];           // w2[d][hm]
    }
    if (tid < HM) sB1[tid] = msg_b1[tid];
    if (tid < 64) sB2[tid] = msg_b2[tid];

    // ---- init: per-cell state (+ feature-major hF) ----
    const size_t base4 = (size_t)bc * 4096;
    for (int idx = htid; idx < 4096; idx += 256) {
        int i = idx >> 6, d = idx & 63;
        float hv = h0[base4 + idx];
        sH  [i * SR + d] = hv;
        sMF [d * SR + i] = hv;
        sHeb[i * SR + d] = heb0[base4 + idx];
    }
    if (htid < 64) {
        sG  [htid] = 0.5f * sigf(dgl[c * 64 + htid]);
        sHg [htid] = 0.5f * sigf(hdl[c * 64 + htid]);
        sWg1[htid] = 1.0f - 0.5f * sigf(Wdl[c * 64 + htid]);
        sDf [htid] = 1.0f;
        sXt [htid] = x[(((size_t)b * TT + 0) * NCELL + c) * 64 + htid];
    }
    if (htid < AA) {
        sIP[htid]     = ipi[c * AA + htid];
        sIP[4 + htid] = opi[c * AA + htid];
    }
    __syncthreads();

    const int ti = htid >> 4;      // 0..15
    const int tj = htid & 15;      // 0..15
    const int r0 = ti * 4;         // 4 rows per thread
    // output columns: tj + 16*cc  (strided -> tj-varying operand rows 1 apart: 2-way max)
    const float* Wbase = W0 + base4;

    for (int t = 0; t < TT; ++t) {
        // ---- P0: stage W0 -> sH2 (coalesced); injection ----
        #pragma unroll
        for (int q = 0; q < 4; ++q) {
            int lin = q * 256 + htid;
            int i = lin >> 4, col = (lin & 15) * 4;
            float4 w = __ldg((const float4*)(Wbase + i * 64 + col));
            *(float4*)&sH2[i * SR + col] = w;
        }
        {
            int aa = htid >> 6, d = htid & 63;
            int row = aa * 64 + d;
            const float4* wr  = (const float4*)(inject_w + ((size_t)c * 256 + row) * 64);
            const float4* xt4 = (const float4*)sXt;
            float s = inject_b[c * 256 + row];
            #pragma unroll 4
            for (int k = 0; k < 16; ++k) {
                float4 w = __ldg(wr + k);
                float4 xv = xt4[k];
                s += w.x * xv.x + w.y * xv.y + w.z * xv.z + w.w * xv.w;
            }
            sInj[htid] = s;
        }
        HBAR();

        // ---- scatter inj onto input ports of h AND hF ----
        if (htid < 64) {
            #pragma unroll
            for (int aa = 0; aa < AA; ++aa) {
                int p = sIP[aa];
                float v = sInj[aa * 64 + htid];
                sH [p * SR + htid] += v;
                sMF[htid * SR + p] += v;
            }
        }
        HBAR();

        // ---- B: m[i][d] = sum_j (df*W0 + heb)[i][j] * hF[d][j]  (f32x2) ----
        u64t accB[4][4];
        {
            #pragma unroll
            for (int ii = 0; ii < 4; ++ii)
                #pragma unroll
                for (int cc = 0; cc < 4; ++cc) accB[ii][cc] = 0ull;
            u64t df2[4];
            #pragma unroll
            for (int ii = 0; ii < 4; ++ii) {
                float dv = sDf[r0 + ii];
                df2[ii] = pk2(dv, dv);
            }
            #pragma unroll 2
            for (int j4 = 0; j4 < 16; ++j4) {
                ull2 hfv[4];
                #pragma unroll
                for (int cc = 0; cc < 4; ++cc)
                    hfv[cc] = *(const ull2*)&sMF[(tj + 16 * cc) * SR + j4 * 4];
                #pragma unroll
                for (int ii = 0; ii < 4; ++ii) {
                    ull2 wv = *(const ull2*)&sH2 [(r0 + ii) * SR + j4 * 4];
                    ull2 hb = *(const ull2*)&sHeb[(r0 + ii) * SR + j4 * 4];
                    u64t f0 = fma2(wv.x, df2[ii], hb.x);
                    u64t f1 = fma2(wv.y, df2[ii], hb.y);
                    #pragma unroll
                    for (int cc = 0; cc < 4; ++cc) {
                        accB[ii][cc] = fma2(f0, hfv[cc].x, accB[ii][cc]);
                        accB[ii][cc] = fma2(f1, hfv[cc].y, accB[ii][cc]);
                    }
                }
            }
        }
        HBAR();   // hF reads done; sMF becomes m

        #pragma unroll
        for (int ii = 0; ii < 4; ++ii)
            #pragma unroll
            for (int cc = 0; cc < 4; ++cc)
                sMF[(r0 + ii) * SR + tj + 16 * cc] = lhsum(accB[ii][cc]);
        HBAR();

        // ---- shared MLP, two hm-halves; hid in sH2 ----
        float accC[4][4];
        #pragma unroll
        for (int ii = 0; ii < 4; ++ii)
            #pragma unroll
            for (int cc = 0; cc < 4; ++cc) accC[ii][cc] = 0.0f;

        #pragma unroll
        for (int half = 0; half < 2; ++half) {
            const int h0c = half * 64;
            // C1: hid[i][u] = tanh(sum_k m[i][k]*w1[h0+u][k] + b1[h0+u]), u = tj+16uu
            {
                u64t a[4][4];
                #pragma unroll
                for (int ii = 0; ii < 4; ++ii)
                    #pragma unroll
                    for (int uu = 0; uu < 4; ++uu) a[ii][uu] = 0ull;
                #pragma unroll 2
                for (int k4 = 0; k4 < 16; ++k4) {
                    ull2 wv[4];
                    #pragma unroll
                    for (int uu = 0; uu < 4; ++uu)
                        wv[uu] = *(const ull2*)&sW1[(h0c + tj + 16 * uu) * W1S + k4 * 4];
                    #pragma unroll
                    for (int ii = 0; ii < 4; ++ii) {
                        ull2 mv = *(const ull2*)&sMF[(r0 + ii) * SR + k4 * 4];
                        #pragma unroll
                        for (int uu = 0; uu < 4; ++uu) {
                            a[ii][uu] = fma2(mv.x, wv[uu].x, a[ii][uu]);
                            a[ii][uu] = fma2(mv.y, wv[uu].y, a[ii][uu]);
                        }
                    }
                }
                #pragma unroll
                for (int ii = 0; ii < 4; ++ii)
                    #pragma unroll
                    for (int uu = 0; uu < 4; ++uu)
                        sH2[(r0 + ii) * SR + tj + 16 * uu] =
                            tanhf(lhsum(a[ii][uu]) + sB1[h0c + tj + 16 * uu]);
            }
            HBAR();
            // C2: accC[i][d] += sum_u hid[i][u]*w2[d][h0+u], d = tj+16cc
            {
                u64t a[4][4];
                #pragma unroll
                for (int ii = 0; ii < 4; ++ii)
                    #pragma unroll
                    for (int cc = 0; cc < 4; ++cc) a[ii][cc] = 0ull;
                #pragma unroll 2
                for (int u4 = 0; u4 < 16; ++u4) {
                    ull2 wv[4];
                    #pragma unroll
                    for (int cc = 0; cc < 4; ++cc)
                        wv[cc] = *(const ull2*)&sW2[(tj + 16 * cc) * W2S + h0c + u4 * 4];
                    #pragma unroll
                    for (int ii = 0; ii < 4; ++ii) {
                        ull2 hv = *(const ull2*)&sH2[(r0 + ii) * SR + u4 * 4];
                        #pragma unroll
                        for (int cc = 0; cc < 4; ++cc) {
                            a[ii][cc] = fma2(hv.x, wv[cc].x, a[ii][cc]);
                            a[ii][cc] = fma2(hv.y, wv[cc].y, a[ii][cc]);
                        }
                    }
                }
                #pragma unroll
                for (int ii = 0; ii < 4; ++ii)
                    #pragma unroll
                    for (int cc = 0; cc < 4; ++cc)
                        accC[ii][cc] += lhsum(a[ii][cc]);
            }
            if (half == 0) HBAR();   // protect sH2 before C1b overwrites hid
        }

        // ---- gated h update; rewrite sH and hF (m in sMF now dead) ----
        #pragma unroll
        for (int ii = 0; ii < 4; ++ii) {
            int r = r0 + ii;
            float g = sG[r];
            const float* nidp = neuron_id + (size_t)c * 4096 + r * 64;
            #pragma unroll
            for (int cc = 0; cc < 4; ++cc) {
                int d = tj + 16 * cc;
                float mm = accC[ii][cc] + sB2[d] + __ldg(nidp + d);
                float hn = (1.0f - g) * sH[r * SR + d] + g * tanhf(mm);
                sH [r * SR + d] = hn;
                sMF[d * SR + r] = hn;
            }
        }
        HBAR();

        // ---- D: heb update via f32x2 dot over d ----
        {
            u64t a[4][4];
            #pragma unroll
            for (int ii = 0; ii < 4; ++ii)
                #pragma unroll
                for (int jj = 0; jj < 4; ++jj) a[ii][jj] = 0ull;
            #pragma unroll 2
            for (int d4 = 0; d4 < 16; ++d4) {
                ull2 vv[4];
                #pragma unroll
                for (int jj = 0; jj < 4; ++jj)
                    vv[jj] = *(const ull2*)&sH[(tj + 16 * jj) * SR + d4 * 4];
                #pragma unroll
                for (int ii = 0; ii < 4; ++ii) {
                    ull2 uv = *(const ull2*)&sH[(r0 + ii) * SR + d4 * 4];
                    #pragma unroll
                    for (int jj = 0; jj < 4; ++jj) {
                        a[ii][jj] = fma2(uv.x, vv[jj].x, a[ii][jj]);
                        a[ii][jj] = fma2(uv.y, vv[jj].y, a[ii][jj]);
                    }
                }
            }
            #pragma unroll
            for (int ii = 0; ii < 4; ++ii) {
                int i = r0 + ii;
                float hg1 = 1.0f - sHg[i];
                float hgs = sHg[i] * (1.0f / 64.0f);
                #pragma unroll
                for (int jj = 0; jj < 4; ++jj) {
                    int j = tj + 16 * jj;
                    float nh = hg1 * sHeb[i * SR + j] + hgs * lhsum(a[ii][jj]);
                    sHeb[i * SR + j] = (j == i) ? 0.0f : nh;
                }
            }
        }

        // ---- readout / decay / next-xt prefetch ----
        if (htid < 64) {
            float s = 0.0f;
            #pragma unroll
            for (int aa = 0; aa < AA; ++aa)
                s += sH[sIP[4 + aa] * SR + htid];
            out[(((size_t)b * TT + t) * NCELL + c) * 64 + htid] = 0.125f * s;
        } else if (htid < 128) {
            sDf[htid - 64] *= sWg1[htid - 64];
        } else if (htid >= 192 && t + 1 < TT) {
            sXt[htid - 192] = x[(((size_t)b * TT + t + 1) * NCELL + c) * 64 + (htid - 192)];
        }
        HBAR();
    }
}

extern "C" void kernel_launch(void* const* d_in, const int* in_sizes, int n_in,
                              void* d_out, int out_size)
{
    (void)in_sizes; (void)n_in; (void)out_size;
    const float* x         = (const float*)d_in[0];
    const float* h0        = (const float*)d_in[1];
    const float* W0        = (const float*)d_in[2];
    const float* heb0      = (const float*)d_in[3];
    const float* neuron_id = (const float*)d_in[4];
    const float* msg_w1    = (const float*)d_in[5];
    const float* msg_b1    = (const float*)d_in[6];
    const float* msg_w2    = (const float*)d_in[7];
    const float* msg_b2    = (const float*)d_in[8];
    const float* inject_w  = (const float*)d_in[9];
    const float* inject_b  = (const float*)d_in[10];
    const float* Wdl       = (const float*)d_in[11];
    const float* dgl       = (const float*)d_in[12];
    const float* hdl       = (const float*)d_in[13];
    const int*   ipi       = (const int*)d_in[14];
    const int*   opi       = (const int*)d_in[15];
    float* out = (float*)d_out;

    size_t smem_bytes = (size_t)SMEMF * sizeof(float);   // 213,312 B
    cudaFuncSetAttribute(memgraph_kernel,
                         cudaFuncAttributeMaxDynamicSharedMemorySize,
                         (int)smem_bytes);

    memgraph_kernel<<<(BB * NCELL) / 2, NTHR, smem_bytes>>>(
        x, h0, W0, heb0, neuron_id, msg_w1, msg_b1, msg_w2, msg_b2,
        inject_w, inject_b, Wdl, dgl, hdl, ipi, opi, out);
}